// round 2
// baseline (speedup 1.0000x reference)
#include <cuda_runtime.h>
#include <cuda_bf16.h>

#define IMG_W 1024
#define IMG_H 1024
#define NC_TOTAL 48   // 16 batch * 3 channels

// 4x4 register-blocked normalized depthwise 3x3 conv.
// Thread: 4 consecutive pixels (float4) x 4 output rows.
// Horizontal halo via warp shuffle (scalar loads only at lane 0/31).
// 6 input-row loads serve 4 output rows (1.5x reads/row vs 3x before).
__global__ void __launch_bounds__(256) normconv3x3_v2(
    const float* __restrict__ x,
    const float* __restrict__ wt,
    float* __restrict__ out)
{
    const int lane = threadIdx.x & 31;
    const int x0 = (int)threadIdx.x << 2;          // 0..1020 (256 threads * 4 px = 1024)
    const int b = blockIdx.x;
    const int y0 = (b & 255) << 2;                 // 256 row-tiles of 4
    const int nc = b >> 8;                         // 0..47
    const int c = nc % 3;

    // Normalized per-channel 3x3 weights (const-cache broadcast)
    float w[9];
    float s2 = 0.f;
#pragma unroll
    for (int k = 0; k < 9; k++) { w[k] = __ldg(&wt[c * 9 + k]); s2 += w[k] * w[k]; }
    const float winv = rsqrtf(s2);
#pragma unroll
    for (int k = 0; k < 9; k++) w[k] *= winv;

    const float* base = x + ((size_t)nc << 20) + x0;

    float num[4][4], sq[4][4];
#pragma unroll
    for (int o = 0; o < 4; o++)
#pragma unroll
        for (int j = 0; j < 4; j++) { num[o][j] = 0.f; sq[o][j] = 0.f; }

#pragma unroll
    for (int r = 0; r < 6; r++) {
        const int rr = y0 - 1 + r;
        const bool valid = (rr >= 0) && (rr < IMG_H);
        const float* rp = base + (size_t)rr * IMG_W;

        float4 v = make_float4(0.f, 0.f, 0.f, 0.f);
        if (valid) v = *reinterpret_cast<const float4*>(rp);

        // Horizontal halo from neighbor lanes; boundary lanes load scalars.
        float a0 = __shfl_up_sync(0xffffffffu, v.w, 1);
        float a5 = __shfl_down_sync(0xffffffffu, v.x, 1);
        if (lane == 0)  a0 = (valid && x0 > 0)           ? __ldg(rp - 1) : 0.f;
        if (lane == 31) a5 = (valid && x0 + 4 < IMG_W)   ? __ldg(rp + 4) : 0.f;

        const float a[6] = { a0, v.x, v.y, v.z, v.w, a5 };

        // Per-row squared-window sums (shared across the <=3 output rows this row feeds)
        float p[6];
#pragma unroll
        for (int i = 0; i < 6; i++) p[i] = a[i] * a[i];
        const float u = p[1] + p[2];
        const float t = p[3] + p[4];
        float s[4];
        s[0] = p[0] + u;
        s[1] = u + p[3];
        s[2] = p[2] + t;
        s[3] = t + p[5];

#pragma unroll
        for (int o = 0; o < 4; o++) {
            const int k = r - o;                    // weight row for this (input,output) pair
            if (k >= 0 && k <= 2) {
                const float w0 = w[k * 3 + 0], w1 = w[k * 3 + 1], w2 = w[k * 3 + 2];
#pragma unroll
                for (int j = 0; j < 4; j++) {
                    num[o][j] = fmaf(w0, a[j], fmaf(w1, a[j + 1], fmaf(w2, a[j + 2], num[o][j])));
                    sq[o][j] += s[j];
                }
            }
        }
    }

    float* op = out + ((size_t)nc << 20) + (size_t)y0 * IMG_W + x0;
#pragma unroll
    for (int o = 0; o < 4; o++) {
        float4 ov;
        ov.x = num[o][0] * rsqrtf(sq[o][0]);
        ov.y = num[o][1] * rsqrtf(sq[o][1]);
        ov.z = num[o][2] * rsqrtf(sq[o][2]);
        ov.w = num[o][3] * rsqrtf(sq[o][3]);
        *reinterpret_cast<float4*>(op + (size_t)o * IMG_W) = ov;
    }
}

extern "C" void kernel_launch(void* const* d_in, const int* in_sizes, int n_in,
                              void* d_out, int out_size) {
    const float* x  = (const float*)d_in[0];
    const float* wt = (const float*)d_in[1];
    float* out = (float*)d_out;

    // block = 256 threads = full 1024-px row width; grid = 48 nc * 256 row-tiles
    dim3 grid(NC_TOTAL * (IMG_H / 4));
    normconv3x3_v2<<<grid, 256>>>(x, wt, out);
}

// round 3
// speedup vs baseline: 1.2615x; 1.2615x over previous
#include <cuda_runtime.h>
#include <cuda_bf16.h>

#define IMG_W 1024
#define IMG_H 1024
#define NC_TOTAL 48   // 16 batch * 3 channels

// 4-row x 4-px register-blocked normalized depthwise 3x3 conv.
// All 6 input-row loads issued branch-free up front (clamped index + mask)
// so they batch into one MLP-6 group; halo via warp shuffle.
__global__ void __launch_bounds__(256, 3) normconv3x3_v3(
    const float* __restrict__ x,
    const float* __restrict__ wt,
    float* __restrict__ out)
{
    const int lane = threadIdx.x & 31;
    const int x0 = (int)threadIdx.x << 2;          // 0..1020
    const int b = blockIdx.x;
    const int y0 = (b & 255) << 2;                 // 4-row tiles
    const int nc = b >> 8;                         // 0..47
    const int c = nc % 3;

    // Normalized per-channel 3x3 weights (const-cache broadcast)
    float w[9];
    float s2 = 0.f;
#pragma unroll
    for (int k = 0; k < 9; k++) { w[k] = __ldg(&wt[c * 9 + k]); s2 += w[k] * w[k]; }
    const float winv = rsqrtf(s2);
#pragma unroll
    for (int k = 0; k < 9; k++) w[k] *= winv;

    const float* base = x + ((size_t)nc << 20) + x0;

    // ---- Phase 1: branch-free batched loads of 6 rows ----
    float4 v[6];
    float msk[6];
    int rrc[6];
#pragma unroll
    for (int r = 0; r < 6; r++) {
        const int rr = y0 - 1 + r;
        rrc[r] = min(IMG_H - 1, max(0, rr));
        v[r] = *reinterpret_cast<const float4*>(base + (size_t)rrc[r] * IMG_W);
        msk[r] = (rr == rrc[r]) ? 1.f : 0.f;
    }
#pragma unroll
    for (int r = 0; r < 6; r++) {
        v[r].x *= msk[r]; v[r].y *= msk[r]; v[r].z *= msk[r]; v[r].w *= msk[r];
    }

    // ---- Phase 2: batched shuffles for horizontal halo ----
    float h0[6], h5[6];
#pragma unroll
    for (int r = 0; r < 6; r++) {
        h0[r] = __shfl_up_sync(0xffffffffu, v[r].w, 1);
        h5[r] = __shfl_down_sync(0xffffffffu, v[r].x, 1);
    }
    // lane-boundary fixes (x0==0 / x0==1020 are image edges -> zero)
    if (lane == 0) {
#pragma unroll
        for (int r = 0; r < 6; r++)
            h0[r] = (x0 > 0) ? __ldg(base + (size_t)rrc[r] * IMG_W - 1) * msk[r] : 0.f;
    }
    if (lane == 31) {
#pragma unroll
        for (int r = 0; r < 6; r++)
            h5[r] = (x0 + 4 < IMG_W) ? __ldg(base + (size_t)rrc[r] * IMG_W + 4) * msk[r] : 0.f;
    }

    // ---- Phase 3: pure-FMA compute ----
    float num[4][4], sq[4][4];
#pragma unroll
    for (int o = 0; o < 4; o++)
#pragma unroll
        for (int j = 0; j < 4; j++) { num[o][j] = 0.f; sq[o][j] = 0.f; }

#pragma unroll
    for (int r = 0; r < 6; r++) {
        const float a[6] = { h0[r], v[r].x, v[r].y, v[r].z, v[r].w, h5[r] };

        float p[6];
#pragma unroll
        for (int i = 0; i < 6; i++) p[i] = a[i] * a[i];
        const float u = p[1] + p[2];
        const float t = p[3] + p[4];
        float s[4];
        s[0] = p[0] + u;
        s[1] = u + p[3];
        s[2] = p[2] + t;
        s[3] = t + p[5];

#pragma unroll
        for (int o = 0; o < 4; o++) {
            const int k = r - o;                    // weight row index
            if (k >= 0 && k <= 2) {
                const float w0 = w[k * 3 + 0], w1 = w[k * 3 + 1], w2 = w[k * 3 + 2];
#pragma unroll
                for (int j = 0; j < 4; j++) {
                    num[o][j] = fmaf(w0, a[j], fmaf(w1, a[j + 1], fmaf(w2, a[j + 2], num[o][j])));
                    sq[o][j] += s[j];
                }
            }
        }
    }

    float* op = out + ((size_t)nc << 20) + (size_t)y0 * IMG_W + x0;
#pragma unroll
    for (int o = 0; o < 4; o++) {
        float4 ov;
        ov.x = num[o][0] * rsqrtf(sq[o][0]);
        ov.y = num[o][1] * rsqrtf(sq[o][1]);
        ov.z = num[o][2] * rsqrtf(sq[o][2]);
        ov.w = num[o][3] * rsqrtf(sq[o][3]);
        *reinterpret_cast<float4*>(op + (size_t)o * IMG_W) = ov;
    }
}

extern "C" void kernel_launch(void* const* d_in, const int* in_sizes, int n_in,
                              void* d_out, int out_size) {
    const float* x  = (const float*)d_in[0];
    const float* wt = (const float*)d_in[1];
    float* out = (float*)d_out;

    dim3 grid(NC_TOTAL * (IMG_H / 4));   // 12288 blocks, 256 threads = one full row-width
    normconv3x3_v3<<<grid, 256>>>(x, wt, out);
}

// round 4
// speedup vs baseline: 1.2911x; 1.0234x over previous
#include <cuda_runtime.h>
#include <cuda_bf16.h>

#define IMG_W 1024
#define IMG_H 1024
#define NC_TOTAL 48   // 16 batch * 3 channels

// 4-row x 4-px register-blocked normalized depthwise 3x3 conv, v4.
// - 6 row loads front-batched (MLP=6), branch-free on the 254/256 interior tiles
// - uniform per-block slow path only for the top/bottom row-tiles
// - shuffle halo inline; output row stored as soon as complete (reg pressure)
// - launch_bounds(256,4): 64-reg cap -> 32 warps/SM
__global__ void __launch_bounds__(256, 4) normconv3x3_v4(
    const float* __restrict__ x,
    const float* __restrict__ wt,
    float* __restrict__ out)
{
    const int lane = threadIdx.x & 31;
    const int x0 = (int)threadIdx.x << 2;          // 0..1020
    const int b = blockIdx.x;
    const int y0 = (b & 255) << 2;                 // 4-row tiles
    const int nc = b >> 8;                         // 0..47
    const int c = nc % 3;

    // Normalized per-channel 3x3 weights (const-cache broadcast)
    float w[9];
    float s2 = 0.f;
#pragma unroll
    for (int k = 0; k < 9; k++) { w[k] = __ldg(&wt[c * 9 + k]); s2 += w[k] * w[k]; }
    const float winv = rsqrtf(s2);
#pragma unroll
    for (int k = 0; k < 9; k++) w[k] *= winv;

    const float* base = x + ((size_t)nc << 20) + x0;

    // ---- Phase 1: batched loads of 6 rows ----
    float4 v[6];
    if (y0 != 0 && y0 != IMG_H - 4) {
        // interior tile: no clamp, no mask (uniform branch; 254/256 of blocks)
#pragma unroll
        for (int r = 0; r < 6; r++)
            v[r] = *reinterpret_cast<const float4*>(base + (size_t)(y0 - 1 + r) * IMG_W);
    } else {
#pragma unroll
        for (int r = 0; r < 6; r++) {
            const int rr = y0 - 1 + r;
            const int rc = min(IMG_H - 1, max(0, rr));
            v[r] = *reinterpret_cast<const float4*>(base + (size_t)rc * IMG_W);
            if (rr != rc) v[r] = make_float4(0.f, 0.f, 0.f, 0.f);
        }
    }

    // ---- Phase 2: per-row shuffle halo + compute, early store ----
    float num[4][4], sq[4][4];
#pragma unroll
    for (int o = 0; o < 4; o++)
#pragma unroll
        for (int j = 0; j < 4; j++) { num[o][j] = 0.f; sq[o][j] = 0.f; }

    float* op = out + ((size_t)nc << 20) + (size_t)y0 * IMG_W + x0;

#pragma unroll
    for (int r = 0; r < 6; r++) {
        float a0 = __shfl_up_sync(0xffffffffu, v[r].w, 1);
        float a5 = __shfl_down_sync(0xffffffffu, v[r].x, 1);
        if (lane == 0) {
            a0 = 0.f;
            if (x0 > 0) {
                const int rr = y0 - 1 + r;
                const int rc = min(IMG_H - 1, max(0, rr));
                a0 = (rr == rc) ? __ldg(base + (size_t)rc * IMG_W - 1) : 0.f;
            }
        }
        if (lane == 31) {
            a5 = 0.f;
            if (x0 + 4 < IMG_W) {
                const int rr = y0 - 1 + r;
                const int rc = min(IMG_H - 1, max(0, rr));
                a5 = (rr == rc) ? __ldg(base + (size_t)rc * IMG_W + 4) : 0.f;
            }
        }

        const float a[6] = { a0, v[r].x, v[r].y, v[r].z, v[r].w, a5 };

        float p[6];
#pragma unroll
        for (int i = 0; i < 6; i++) p[i] = a[i] * a[i];
        const float u = p[1] + p[2];
        const float t = p[3] + p[4];
        float s[4];
        s[0] = p[0] + u;
        s[1] = u + p[3];
        s[2] = p[2] + t;
        s[3] = t + p[5];

#pragma unroll
        for (int o = 0; o < 4; o++) {
            const int k = r - o;                    // weight row index
            if (k >= 0 && k <= 2) {
                const float w0 = w[k * 3 + 0], w1 = w[k * 3 + 1], w2 = w[k * 3 + 2];
#pragma unroll
                for (int j = 0; j < 4; j++) {
                    num[o][j] = fmaf(w0, a[j], fmaf(w1, a[j + 1], fmaf(w2, a[j + 2], num[o][j])));
                    sq[o][j] += s[j];
                }
            }
        }

        // output row (r-2) is complete after consuming input row r
        if (r >= 2) {
            const int o = r - 2;
            float4 ov;
            ov.x = num[o][0] * rsqrtf(sq[o][0]);
            ov.y = num[o][1] * rsqrtf(sq[o][1]);
            ov.z = num[o][2] * rsqrtf(sq[o][2]);
            ov.w = num[o][3] * rsqrtf(sq[o][3]);
            *reinterpret_cast<float4*>(op + (size_t)o * IMG_W) = ov;
        }
    }
}

extern "C" void kernel_launch(void* const* d_in, const int* in_sizes, int n_in,
                              void* d_out, int out_size) {
    const float* x  = (const float*)d_in[0];
    const float* wt = (const float*)d_in[1];
    float* out = (float*)d_out;

    dim3 grid(NC_TOTAL * (IMG_H / 4));   // 12288 blocks, 256 threads = one full row-width
    normconv3x3_v4<<<grid, 256>>>(x, wt, out);
}